// round 13
// baseline (speedup 1.0000x reference)
#include <cuda_runtime.h>
#include <math.h>
#include <stdint.h>

#define Bv 64
#define Tv 256
#define Ev 300
#define EP 304          // padded K for the input GEMMs (zeros in pad cols)
#define Hv 512
#define Ov 5
#define PADTOK 1
#define GROWS 2048      // 4*H gate rows
#define NCTA 128        // recurrent CTAs; each owns 4 hidden units = 16 gate rows

typedef unsigned long long ull;

// ---------------- scratch (static device allocations; no cudaMalloc) ----------------
__device__ float g_inp [Tv*Bv*EP];                 // [t][b][e], e padded to 304, pad = 0
__device__ float g_ig  [Tv*NCTA*16*Bv];            // [t][c][rr][b]  (rr = u*4+q)
__device__ float g_Wblk[NCTA*Hv*16];               // [c][k][rr]
__device__ float g_hA  [Hv*Bv];                    // h ping  [j][b]
__device__ float g_hB  [Hv*Bv];                    // h pong  [j][b]
__device__ float g_last[Bv*Hv];                    // [b][j]
__device__ float g_att [Tv*Bv];                    // [t][b]
__device__ float g_part2[Bv*Ev];                   // [b][e]
__device__ float g_H1  [Tv*Bv*Ev];                 // [m][e]  tanh(layer1)
__device__ int   g_len [Bv];
__device__ int   g_bar;                            // grid barrier counter

__device__ __forceinline__ float sigf(float x) { return 1.f / (1.f + expf(-x)); }

__device__ __forceinline__ uint32_t smem_u32(const void* p) {
    uint32_t a;
    asm("{ .reg .u64 t; cvta.to.shared.u64 t, %1; cvt.u32.u64 %0, t; }" : "=r"(a) : "l"(p));
    return a;
}

// ---- packed fp32x2 helpers (sm_103a FFMA2 path; full fp32 per lane) ----
__device__ __forceinline__ ull pk2(float x, float y) {
    ull r; asm("mov.b64 %0, {%1, %2};" : "=l"(r) : "f"(x), "f"(y)); return r;
}
__device__ __forceinline__ void upk2(ull v, float& x, float& y) {
    asm("mov.b64 {%0, %1}, %2;" : "=f"(x), "=f"(y) : "l"(v));
}
__device__ __forceinline__ void fma2(ull& d, ull a, ull b) {
    asm("fma.rn.f32x2 %0, %1, %2, %0;" : "+l"(d) : "l"(a), "l"(b));
}

// ---------------- tiny kernels ----------------
__global__ void k_len(const int* __restrict__ x) {
    int b = threadIdx.x;
    if (b < Bv) {
        int c = 0;
        for (int t = 0; t < Tv; t++) c += (x[b*Tv + t] != PADTOK);
        g_len[b] = c;
    }
}

__global__ void k_embed(const float* __restrict__ emb, const int* __restrict__ x) {
    int idx = blockIdx.x * blockDim.x + threadIdx.x;
    if (idx >= Tv*Bv*EP) return;
    int e = idx % EP;
    int m = idx / EP;
    int b = m % Bv;
    int t = m / Bv;
    float v = 0.f;
    if (e < Ev) {
        int tok = x[b*Tv + t];
        if (tok != PADTOK) v = emb[(size_t)tok*Ev + e];   // padding_idx row -> 0
    }
    g_inp[idx] = v;
}

// permute W_hh[2048][512] -> g_Wblk[c][k][rr], rr = u*4+q, row = (4c+u) + q*512
__global__ void k_wblk(const float* __restrict__ Whh) {
    int idx = blockIdx.x * blockDim.x + threadIdx.x;
    if (idx >= NCTA*Hv*16) return;
    int rr = idx & 15;
    int k  = (idx >> 4) & (Hv - 1);
    int c  = idx >> 13;
    int u = rr >> 2, q = rr & 3;
    int r = (c*4 + u) + q*Hv;
    g_Wblk[idx] = Whh[(size_t)r*Hv + k];
}

__global__ void k_zero() {
    int i = blockIdx.x * blockDim.x + threadIdx.x;
    if (i == 0) g_bar = 0;
    if (i < Hv*Bv) g_hA[i] = 0.f;
}

__global__ void k_reinit() {   // h <- last (transposed) for iteration 1
    int i = blockIdx.x * blockDim.x + threadIdx.x;
    if (i == 0) g_bar = 0;
    if (i < Hv*Bv) {
        int j = i >> 6, b = i & 63;
        g_hA[i] = g_last[b*Hv + j];
    }
}

// ---------------- time-parallel GEMM: C[m][n] = sum_k g_inp[m][k] * B[n][k] ----------------
__global__ void k_gemm(const float* __restrict__ B, const float* __restrict__ bias1,
                       const float* __restrict__ bias2, int N, int ldb, int mode) {
    __shared__ float As[16][68];
    __shared__ float Bs[16][68];
    int tid = threadIdx.x;
    int m0 = blockIdx.y * 64, n0 = blockIdx.x * 64;
    int tm = tid >> 2, ks = tid & 3;
    int tx = tid & 15, ty = tid >> 4;
    ull acc2[4][2] = {};

    for (int k0 = 0; k0 < EP; k0 += 16) {
        float4 a4 = *(const float4*)&g_inp[(size_t)(m0 + tm)*EP + k0 + ks*4];
        As[ks*4+0][tm] = a4.x; As[ks*4+1][tm] = a4.y;
        As[ks*4+2][tm] = a4.z; As[ks*4+3][tm] = a4.w;
        int n = n0 + tm;
        #pragma unroll
        for (int i = 0; i < 4; i++) {
            int k = k0 + ks*4 + i;
            float v = 0.f;
            if (n < N && k < Ev) v = B[(size_t)n*ldb + k];
            Bs[ks*4+i][tm] = v;
        }
        __syncthreads();
        #pragma unroll
        for (int kk = 0; kk < 16; kk++) {
            float4 a = *(const float4*)&As[kk][ty*4];
            const ull* bp = (const ull*)&Bs[kk][tx*4];
            ull b01 = bp[0], b23 = bp[1];
            ull ax = pk2(a.x, a.x), ay = pk2(a.y, a.y);
            ull az = pk2(a.z, a.z), aw = pk2(a.w, a.w);
            fma2(acc2[0][0], ax, b01); fma2(acc2[0][1], ax, b23);
            fma2(acc2[1][0], ay, b01); fma2(acc2[1][1], ay, b23);
            fma2(acc2[2][0], az, b01); fma2(acc2[2][1], az, b23);
            fma2(acc2[3][0], aw, b01); fma2(acc2[3][1], aw, b23);
        }
        __syncthreads();
    }

    float acc[4][4];
    #pragma unroll
    for (int i = 0; i < 4; i++) {
        upk2(acc2[i][0], acc[i][0], acc[i][1]);
        upk2(acc2[i][1], acc[i][2], acc[i][3]);
    }

    #pragma unroll
    for (int i = 0; i < 4; i++) {
        int m = m0 + ty*4 + i;
        int t = m >> 6, b = m & 63;
        #pragma unroll
        for (int j = 0; j < 4; j++) {
            int n = n0 + tx*4 + j;
            if (mode == 0) {
                float v = acc[i][j] + bias1[n] + bias2[n];
                int q = n >> 9, jj = n & (Hv - 1);
                int cc = jj >> 2, u = jj & 3, rr = u*4 + q;
                g_ig[(((size_t)t*NCTA + cc)*16 + rr)*64 + b] = v;
            } else if (n < Ev) {
                g_H1[(size_t)m*Ev + n] = tanhf(acc[i][j] + g_part2[b*Ev + n]);
            }
        }
    }
}

// part2[b][e] = ab1[e] + sum_k last[b][k] * aW1[e][300+k]
__global__ void k_part2(const float* __restrict__ aW1, const float* __restrict__ ab1) {
    int wid = (blockIdx.x * blockDim.x + threadIdx.x) >> 5;
    int lane = threadIdx.x & 31;
    if (wid >= Bv*Ev) return;
    int b = wid / Ev, e = wid % Ev;
    const float* lp = g_last + b*Hv;
    const float* wp = aW1 + (size_t)e*(Ev + Hv) + Ev;
    float s = 0.f;
    for (int k = lane; k < Hv; k += 32) s += lp[k] * wp[k];
    #pragma unroll
    for (int o = 16; o; o >>= 1) s += __shfl_xor_sync(0xffffffffu, s, o);
    if (!lane) g_part2[b*Ev + e] = s + ab1[e];
}

// att[m] = sigmoid(ab2 + sum_e H1[m][e]*aW2[e])
__global__ void k_att(const float* __restrict__ aW2, const float* __restrict__ ab2) {
    int wid = (blockIdx.x * blockDim.x + threadIdx.x) >> 5;
    int lane = threadIdx.x & 31;
    if (wid >= Tv*Bv) return;
    const float* hp = g_H1 + (size_t)wid*Ev;
    float s = 0.f;
    for (int e = lane; e < Ev; e += 32) s += hp[e] * aW2[e];
    #pragma unroll
    for (int o = 16; o; o >>= 1) s += __shfl_xor_sync(0xffffffffu, s, o);
    if (!lane) g_att[wid] = sigf(s + ab2[0]);
}

// ---------------- persistent recurrent kernel ----------------
// 128 CTAs x 128 threads. CTA c owns hidden units 4c..4c+3 (16 gate rows).
// Thread (g = tid>>6, b = tid&63) owns gate rows rr=g*8..g*8+7 (= 2 hidden
// units, all 4 gates) for one batch element -> cell state lives in registers.
__device__ __forceinline__ void cp_chunk32k(uint32_t sdst, const float* gsrc, int tid) {
    const char* g = (const char*)gsrc + tid*16;
    uint32_t s = sdst + tid*16;
    #pragma unroll
    for (int i = 0; i < 16; i++)
        asm volatile("cp.async.cg.shared.global [%0], [%1], 16;\n"
                     :: "r"(s + i*2048), "l"(g + i*2048));
    asm volatile("cp.async.commit_group;\n" ::: "memory");
}

__global__ void __launch_bounds__(128, 1) k_persist(int use_att) {
    extern __shared__ float sm[];
    float* Wsm = sm;                  // 8192 : [k][rr] for this CTA (32 KB)
    float* Hb  = sm + 8192;           // 2 x 8192 : h chunk double buffer (2 x 32 KB)
    int*   len = (int*)(sm + 24576);  // 64

    int tid = threadIdx.x;
    int g = tid >> 6, b = tid & 63;
    int c = blockIdx.x;
    uint32_t hb_u32 = smem_u32(Hb);

    { // resident W load (once per launch, reused 256 steps)
        const float4* ws = (const float4*)(g_Wblk + (size_t)c*8192);
        float4* wd = (float4*)Wsm;
        #pragma unroll
        for (int i = tid; i < 2048; i += 128) wd[i] = ws[i];
    }
    if (tid < 64) len[tid] = g_len[tid];
    __syncthreads();

    int j0 = c*4 + g*2;                       // first of this thread's 2 hidden units
    float c0 = 0.f, c1 = 0.f;
    float hp0 = g_hA[j0*64 + b];
    float hp1 = g_hA[(j0 + 1)*64 + b];
    int lim = len[b] - 1;

    for (int t = 0; t < Tv; t++) {
        const float* hin  = (t & 1) ? g_hB : g_hA;
        float*       hout = (t & 1) ? g_hA : g_hB;

        // input-side gates (latency hidden: consumed only after the k-loop)
        const float* igc = g_ig + ((size_t)t*NCTA + c)*1024 + g*512 + b;
        float igv[8];
        #pragma unroll
        for (int i = 0; i < 8; i++) igv[i] = igc[i*64];

        ull acc0 = 0, acc1 = 0, acc2 = 0, acc3 = 0;

        cp_chunk32k(hb_u32, hin, tid);      // prefetch chunk 0
        #pragma unroll 1
        for (int ch = 0; ch < 4; ch++) {
            __syncthreads();                 // target buffer free
            if (ch < 3) {
                cp_chunk32k(hb_u32 + (((ch + 1) & 1) * 8192u) * 4u, hin + (ch + 1)*8192, tid);
                asm volatile("cp.async.wait_group 1;\n" ::: "memory");
            } else {
                asm volatile("cp.async.wait_group 0;\n" ::: "memory");
            }
            __syncthreads();                 // chunk visible
            const float* Hs = Hb + (ch & 1)*8192;
            const float* Wp = Wsm + ch*2048 + g*8;
            #pragma unroll 8
            for (int kk = 0; kk < 128; kk++) {
                float hv = Hs[kk*64 + b];
                ull h2 = pk2(hv, hv);
                const ull* wp = (const ull*)(Wp + kk*16);
                fma2(acc0, wp[0], h2);
                fma2(acc1, wp[1], h2);
                fma2(acc2, wp[2], h2);
                fma2(acc3, wp[3], h2);
            }
        }

        float gv[8];
        upk2(acc0, gv[0], gv[1]); upk2(acc1, gv[2], gv[3]);
        upk2(acc2, gv[4], gv[5]); upk2(acc3, gv[6], gv[7]);
        #pragma unroll
        for (int i = 0; i < 8; i++) gv[i] += igv[i];

        float a = 1.f, am = 0.f;
        if (use_att) { a = g_att[t*64 + b]; am = 1.f - a; }
        {   // unit 0: i=gv0 f=gv1 g=gv2 o=gv3
            float cn = sigf(gv[1])*c0 + sigf(gv[0])*tanhf(gv[2]);
            float hn = sigf(gv[3])*tanhf(cn);
            if (use_att) { hn = a*hn + am*hp0; cn = a*cn + am*c0; }
            c0 = cn; hp0 = hn;
            __stcg(&hout[j0*64 + b], hn);
            if (t == lim) g_last[b*Hv + j0] = hn;
        }
        {   // unit 1
            float cn = sigf(gv[5])*c1 + sigf(gv[4])*tanhf(gv[6]);
            float hn = sigf(gv[7])*tanhf(cn);
            if (use_att) { hn = a*hn + am*hp1; cn = a*cn + am*c1; }
            c1 = cn; hp1 = hn;
            __stcg(&hout[(j0 + 1)*64 + b], hn);
            if (t == lim) g_last[b*Hv + j0 + 1] = hn;
        }
        __syncthreads();   // all stores of this step issued before leader releases

        if (t < Tv - 1) {  // grid barrier (proven R12 form)
            if (tid == 0) {
                __threadfence();
                atomicAdd(&g_bar, 1);
                int tgt = NCTA * (t + 1);
                while (*(volatile int*)&g_bar < tgt) { }
                __threadfence();
            }
            __syncthreads();
        }
    }
}

__global__ void k_logits(const float* __restrict__ Wout, const float* __restrict__ bout,
                         float* __restrict__ out) {
    int wid = (blockIdx.x * blockDim.x + threadIdx.x) >> 5;
    int lane = threadIdx.x & 31;
    if (wid >= Bv*Ov) return;
    int b = wid / Ov, o = wid % Ov;
    float s = 0.f;
    for (int j = lane; j < Hv; j += 32) s += g_last[b*Hv + j] * Wout[(size_t)o*Hv + j];
    #pragma unroll
    for (int off = 16; off; off >>= 1) s += __shfl_xor_sync(0xffffffffu, s, off);
    if (!lane) out[b*Ov + o] = s + bout[o];
}

// ---------------- launch ----------------
extern "C" void kernel_launch(void* const* d_in, const int* in_sizes, int n_in,
                              void* d_out, int out_size) {
    const float* emb  = (const float*)d_in[0];
    const float* Wih  = (const float*)d_in[1];
    const float* bih  = (const float*)d_in[2];
    const float* Whh  = (const float*)d_in[3];
    const float* bhh  = (const float*)d_in[4];
    const float* aW1  = (const float*)d_in[5];
    const float* ab1  = (const float*)d_in[6];
    const float* aW2  = (const float*)d_in[7];
    const float* ab2  = (const float*)d_in[8];
    const float* Wout = (const float*)d_in[9];
    const float* bout = (const float*)d_in[10];
    const int*   x    = (const int*)d_in[11];
    float* out = (float*)d_out;
    (void)in_sizes; (void)n_in; (void)out_size;

    static int smem_set = 0;
    const int PSMEM = (24576 + 64) * 4;
    if (!smem_set) {
        cudaFuncSetAttribute(k_persist, cudaFuncAttributeMaxDynamicSharedMemorySize, PSMEM);
        smem_set = 1;
    }

    k_len<<<1, 64>>>(x);
    k_embed<<<(Tv*Bv*EP + 255)/256, 256>>>(emb, x);
    k_wblk<<<(NCTA*Hv*16 + 255)/256, 256>>>(Whh);

    // one GEMM feeds both iterations (input-side gates are time-invariant across iters)
    dim3 gig(GROWS/64, Tv*Bv/64);
    k_gemm<<<gig, 256>>>(Wih, bih, bhh, GROWS, Ev, 0);

    // ---- iteration 0 (persistent) ----
    k_zero<<<(Hv*Bv + 255)/256, 256>>>();
    k_persist<<<NCTA, 128, PSMEM>>>(0);

    // ---- attention (uses g_last from iter 0) ----
    k_part2<<<(Bv*Ev*32 + 255)/256, 256>>>(aW1, ab1);
    dim3 gh1((Ev + 63)/64, Tv*Bv/64);
    k_gemm<<<gh1, 256>>>(aW1, (const float*)0, (const float*)0, Ev, Ev + Hv, 1);
    k_att<<<(Tv*Bv*32 + 255)/256, 256>>>(aW2, ab2);

    // ---- iteration 1 (persistent) ----
    k_reinit<<<(Hv*Bv + 255)/256, 256>>>();
    k_persist<<<NCTA, 128, PSMEM>>>(1);

    k_logits<<<(Bv*Ov*32 + 255)/256, 256>>>(Wout, bout, out);
}

// round 15
// speedup vs baseline: 1.1700x; 1.1700x over previous
#include <cuda_runtime.h>
#include <math.h>
#include <stdint.h>

#define Bv 64
#define Tv 256
#define Ev 300
#define EP 320          // padded K for the input GEMMs (zeros in pad cols)
#define Hv 512
#define Ov 5
#define PADTOK 1
#define GROWS 2048      // 4*H gate rows
#define NCTA 128        // recurrent CTAs; each owns 4 hidden units = 16 gate rows

// ---------------- scratch (static device allocations; no cudaMalloc) ----------------
__device__ float g_inp [Tv*Bv*EP];                 // [t][b][e], e padded to 320, pad = 0
__device__ float g_Wpad[GROWS*EP];                 // W_ih zero-padded [2048][320]
__device__ float g_Apad[EP*EP];                    // aW1[:,0:300] zero-padded [320][320]
__device__ float g_ig  [Tv*NCTA*16*Bv];            // [t][c][rr][b]  (rr = u*4+q)
__device__ float g_Wblk[NCTA*Hv*16];               // [c][k][rr]
__device__ float g_hA  [Hv*Bv];                    // h ping  [j][b]
__device__ float g_hB  [Hv*Bv];                    // h pong  [j][b]
__device__ float g_last[Bv*Hv];                    // [b][j]
__device__ float g_att [Tv*Bv];                    // [t][b]
__device__ float g_part2[Bv*Ev];                   // [b][e]
__device__ float g_H1  [Tv*Bv*Ev];                 // [m][e]  tanh(layer1)
__device__ int   g_len [Bv];
__device__ int   g_bar;                            // grid barrier counter

__device__ __forceinline__ float sigf(float x) { return 1.f / (1.f + expf(-x)); }

__device__ __forceinline__ uint32_t smem_u32(const void* p) {
    uint32_t a;
    asm("{ .reg .u64 t; cvta.to.shared.u64 t, %1; cvt.u32.u64 %0, t; }" : "=r"(a) : "l"(p));
    return a;
}

// ---------------- tiny kernels ----------------
__global__ void k_len(const int* __restrict__ x) {
    int b = threadIdx.x;
    if (b < Bv) {
        int c = 0;
        for (int t = 0; t < Tv; t++) c += (x[b*Tv + t] != PADTOK);
        g_len[b] = c;
    }
}

__global__ void k_embed(const float* __restrict__ emb, const int* __restrict__ x) {
    int idx = blockIdx.x * blockDim.x + threadIdx.x;
    if (idx >= Tv*Bv*EP) return;
    int e = idx % EP;
    int m = idx / EP;
    int b = m % Bv;
    int t = m / Bv;
    float v = 0.f;
    if (e < Ev) {
        int tok = x[b*Tv + t];
        if (tok != PADTOK) v = emb[(size_t)tok*Ev + e];   // padding_idx row -> 0
    }
    g_inp[idx] = v;
}

__global__ void k_padW(const float* __restrict__ W) {   // [2048][300] -> [2048][320]
    int idx = blockIdx.x * blockDim.x + threadIdx.x;
    if (idx >= GROWS*EP) return;
    int k = idx % EP, n = idx / EP;
    g_Wpad[idx] = (k < Ev) ? W[(size_t)n*Ev + k] : 0.f;
}

__global__ void k_padA(const float* __restrict__ aW1) { // [300][812] cols 0:300 -> [320][320]
    int idx = blockIdx.x * blockDim.x + threadIdx.x;
    if (idx >= EP*EP) return;
    int k = idx % EP, n = idx / EP;
    g_Apad[idx] = (n < Ev && k < Ev) ? aW1[(size_t)n*(Ev + Hv) + k] : 0.f;
}

// permute W_hh[2048][512] -> g_Wblk[c][k][rr], rr = u*4+q, row = (4c+u) + q*512
__global__ void k_wblk(const float* __restrict__ Whh) {
    int idx = blockIdx.x * blockDim.x + threadIdx.x;
    if (idx >= NCTA*Hv*16) return;
    int rr = idx & 15;
    int k  = (idx >> 4) & (Hv - 1);
    int c  = idx >> 13;
    int u = rr >> 2, q = rr & 3;
    int r = (c*4 + u) + q*Hv;
    g_Wblk[idx] = Whh[(size_t)r*Hv + k];
}

__global__ void k_zero() {
    int i = blockIdx.x * blockDim.x + threadIdx.x;
    if (i == 0) g_bar = 0;
    if (i < Hv*Bv) g_hA[i] = 0.f;
}

__global__ void k_reinit() {   // h <- last (transposed) for iteration 1
    int i = blockIdx.x * blockDim.x + threadIdx.x;
    if (i == 0) g_bar = 0;
    if (i < Hv*Bv) {
        int j = i >> 6, b = i & 63;
        g_hA[i] = g_last[b*Hv + j];
    }
}

// ---------------- time-parallel GEMM: C[m][n] = sum_k g_inp[m][k] * Bm[n][k] ----------------
// Bm (resolved DEVICE-side from mode) is zero-padded [Npad][EP].
// mode 0: input gates -> g_ig scatter (+bias). mode 1: attention layer1 -> g_H1.
// K-tile 32, register-staged global prefetch overlapping compute.
__global__ void k_gemm(const float* __restrict__ bias1, const float* __restrict__ bias2,
                       int mode) {
    __shared__ float As[2][32][68];
    __shared__ float Bs[2][32][68];
    const float* __restrict__ Bm = (mode == 0) ? g_Wpad : g_Apad;  // device-side symbol
    int tid = threadIdx.x;
    int m0 = blockIdx.y * 64, n0 = blockIdx.x * 64;
    int lr = tid >> 2;            // 0..63 row within tile
    int lk = (tid & 3) * 8;       // k offset: two float4 at lk, lk+4
    int tx = tid & 15, ty = tid >> 4;
    float acc[4][4] = {};

    const float* Ap = g_inp + (size_t)(m0 + lr)*EP + lk;
    const float* Bp = Bm    + (size_t)(n0 + lr)*EP + lk;

    float4 a0 = *(const float4*)(Ap);
    float4 a1 = *(const float4*)(Ap + 4);
    float4 b0 = *(const float4*)(Bp);
    float4 b1 = *(const float4*)(Bp + 4);

    #pragma unroll 1
    for (int t = 0; t < EP/32; t++) {
        int buf = t & 1;
        As[buf][lk+0][lr] = a0.x; As[buf][lk+1][lr] = a0.y;
        As[buf][lk+2][lr] = a0.z; As[buf][lk+3][lr] = a0.w;
        As[buf][lk+4][lr] = a1.x; As[buf][lk+5][lr] = a1.y;
        As[buf][lk+6][lr] = a1.z; As[buf][lk+7][lr] = a1.w;
        Bs[buf][lk+0][lr] = b0.x; Bs[buf][lk+1][lr] = b0.y;
        Bs[buf][lk+2][lr] = b0.z; Bs[buf][lk+3][lr] = b0.w;
        Bs[buf][lk+4][lr] = b1.x; Bs[buf][lk+5][lr] = b1.y;
        Bs[buf][lk+6][lr] = b1.z; Bs[buf][lk+7][lr] = b1.w;
        __syncthreads();
        if (t + 1 < EP/32) {       // stage next tile (LDG latency overlaps compute)
            int kb = (t + 1) * 32;
            a0 = *(const float4*)(Ap + kb);
            a1 = *(const float4*)(Ap + kb + 4);
            b0 = *(const float4*)(Bp + kb);
            b1 = *(const float4*)(Bp + kb + 4);
        }
        #pragma unroll
        for (int kk = 0; kk < 32; kk++) {
            float4 a = *(const float4*)&As[buf][kk][ty*4];
            float4 bb = *(const float4*)&Bs[buf][kk][tx*4];
            acc[0][0] += a.x*bb.x; acc[0][1] += a.x*bb.y; acc[0][2] += a.x*bb.z; acc[0][3] += a.x*bb.w;
            acc[1][0] += a.y*bb.x; acc[1][1] += a.y*bb.y; acc[1][2] += a.y*bb.z; acc[1][3] += a.y*bb.w;
            acc[2][0] += a.z*bb.x; acc[2][1] += a.z*bb.y; acc[2][2] += a.z*bb.z; acc[2][3] += a.z*bb.w;
            acc[3][0] += a.w*bb.x; acc[3][1] += a.w*bb.y; acc[3][2] += a.w*bb.z; acc[3][3] += a.w*bb.w;
        }
        __syncthreads();
    }

    #pragma unroll
    for (int i = 0; i < 4; i++) {
        int m = m0 + ty*4 + i;
        int t = m >> 6, b = m & 63;
        #pragma unroll
        for (int j = 0; j < 4; j++) {
            int n = n0 + tx*4 + j;
            if (mode == 0) {
                float v = acc[i][j] + bias1[n] + bias2[n];
                int q = n >> 9, jj = n & (Hv - 1);
                int cc = jj >> 2, u = jj & 3, rr = u*4 + q;
                g_ig[(((size_t)t*NCTA + cc)*16 + rr)*64 + b] = v;
            } else if (n < Ev) {
                g_H1[(size_t)m*Ev + n] = tanhf(acc[i][j] + g_part2[b*Ev + n]);
            }
        }
    }
}

// part2[b][e] = ab1[e] + sum_k last[b][k] * aW1[e][300+k]
__global__ void k_part2(const float* __restrict__ aW1, const float* __restrict__ ab1) {
    int wid = (blockIdx.x * blockDim.x + threadIdx.x) >> 5;
    int lane = threadIdx.x & 31;
    if (wid >= Bv*Ev) return;
    int b = wid / Ev, e = wid % Ev;
    const float* lp = g_last + b*Hv;
    const float* wp = aW1 + (size_t)e*(Ev + Hv) + Ev;
    float s = 0.f;
    for (int k = lane; k < Hv; k += 32) s += lp[k] * wp[k];
    #pragma unroll
    for (int o = 16; o; o >>= 1) s += __shfl_xor_sync(0xffffffffu, s, o);
    if (!lane) g_part2[b*Ev + e] = s + ab1[e];
}

// att[m] = sigmoid(ab2 + sum_e H1[m][e]*aW2[e])
__global__ void k_att(const float* __restrict__ aW2, const float* __restrict__ ab2) {
    int wid = (blockIdx.x * blockDim.x + threadIdx.x) >> 5;
    int lane = threadIdx.x & 31;
    if (wid >= Tv*Bv) return;
    const float* hp = g_H1 + (size_t)wid*Ev;
    float s = 0.f;
    for (int e = lane; e < Ev; e += 32) s += hp[e] * aW2[e];
    #pragma unroll
    for (int o = 16; o; o >>= 1) s += __shfl_xor_sync(0xffffffffu, s, o);
    if (!lane) g_att[wid] = sigf(s + ab2[0]);
}

// ---------------- persistent recurrent kernel: all 256 steps in one launch ----------------
// 128 CTAs x 128 threads (R12-proven mapping). W slice resident in SMEM.
// h via global ping-pong, cp.async.cg 32KB chunks double-buffered, software grid barrier.
__device__ __forceinline__ void cp_chunk32k(uint32_t sdst, const float* gsrc, int tid) {
    const char* g = (const char*)gsrc + tid*16;
    uint32_t s = sdst + tid*16;
    #pragma unroll
    for (int i = 0; i < 16; i++)
        asm volatile("cp.async.cg.shared.global [%0], [%1], 16;\n"
                     :: "r"(s + i*2048), "l"(g + i*2048));
    asm volatile("cp.async.commit_group;\n" ::: "memory");
}
#define CP_WAIT(N) asm volatile("cp.async.wait_group " #N ";\n" ::: "memory")

__global__ void __launch_bounds__(128, 1) k_persist(int use_att) {
    extern __shared__ float sm[];
    float* Wsm = sm;                  // 8192 : [k][rr] for this CTA (32 KB)
    float* Hb  = sm + 8192;           // 2 x 8192 : h chunk double buffer (2 x 32 KB)
    float* Gs  = sm + 24576;          // 1024 : gates [rr][b]
    float* csm = sm + 25600;          // 256  : c state [u][b]
    float* hpr = sm + 25856;          // 256  : own previous h [u][b]
    int*   len = (int*)(sm + 26112);  // 64

    int tid = threadIdx.x, w = tid >> 5, lane = tid & 31;
    int c = blockIdx.x;
    uint32_t hb0 = smem_u32(Hb);
    uint32_t hb1 = hb0 + 32768u;

    { // resident W load (once per launch, reused 256 steps)
        const float4* ws = (const float4*)(g_Wblk + (size_t)c*8192);
        float4* wd = (float4*)Wsm;
        #pragma unroll
        for (int i = tid; i < 2048; i += 128) wd[i] = ws[i];
    }
    for (int idx = tid; idx < 256; idx += 128) {
        csm[idx] = 0.f;
        int u = idx >> 6, b = idx & 63;
        hpr[idx] = g_hA[(c*4 + u)*64 + b];
    }
    if (tid < 64) len[tid] = g_len[tid];
    __syncthreads();

    for (int t = 0; t < Tv; t++) {
        const float* hin  = (t & 1) ? g_hB : g_hA;
        float*       hout = (t & 1) ? g_hA : g_hB;

        // input-side gates (latency hidden: consumed only after the k-loop)
        const float* igc = g_ig + ((size_t)t*NCTA + c)*1024;
        float2 ig[4];
        #pragma unroll
        for (int i = 0; i < 4; i++)
            ig[i] = *(const float2*)&igc[(w*4 + i)*64 + 2*lane];

        float acc[4][2] = {};

        // issue chunks 0 and 1 immediately (buffers free per previous step-end sync)
        cp_chunk32k(hb0, hin, tid);
        cp_chunk32k(hb1, hin + 8192, tid);

        #pragma unroll
        for (int ch = 0; ch < 4; ch++) {
            if (ch == 1) {            // buf0 fully consumed (sync below) -> stage chunk 2
                cp_chunk32k(hb0, hin + 16384, tid);
            } else if (ch == 2) {     // buf1 fully consumed -> stage chunk 3
                cp_chunk32k(hb1, hin + 24576, tid);
            }
            if (ch < 3) { CP_WAIT(1); } else { CP_WAIT(0); }
            __syncthreads();          // chunk ch visible to all threads
            const float* Hs = Hb + (ch & 1)*8192;
            const float* Wp = Wsm + ch*2048 + w*4;
            #pragma unroll 8
            for (int kk = 0; kk < 128; kk++) {
                float2 h2 = *(const float2*)&Hs[kk*64 + 2*lane];
                float4 w4 = *(const float4*)&Wp[kk*16];
                acc[0][0] += w4.x*h2.x; acc[0][1] += w4.x*h2.y;
                acc[1][0] += w4.y*h2.x; acc[1][1] += w4.y*h2.y;
                acc[2][0] += w4.z*h2.x; acc[2][1] += w4.z*h2.y;
                acc[3][0] += w4.w*h2.x; acc[3][1] += w4.w*h2.y;
            }
            if (ch < 3) __syncthreads();  // all threads done with this buffer before reuse
        }

        // stage gates
        #pragma unroll
        for (int i = 0; i < 4; i++) {
            Gs[(w*4 + i)*64 + 2*lane]     = acc[i][0] + ig[i].x;
            Gs[(w*4 + i)*64 + 2*lane + 1] = acc[i][1] + ig[i].y;
        }
        __syncthreads();

        // LSTM cell (+ optional attention gate)
        for (int idx = tid; idx < 256; idx += 128) {
            int u = idx >> 6, b = idx & 63;
            float gi = Gs[(u*4 + 0)*64 + b];
            float gf = Gs[(u*4 + 1)*64 + b];
            float gg = Gs[(u*4 + 2)*64 + b];
            float go = Gs[(u*4 + 3)*64 + b];
            int j = c*4 + u;
            float cold = csm[idx];
            float cn = sigf(gf)*cold + sigf(gi)*tanhf(gg);
            float hn = sigf(go)*tanhf(cn);
            if (use_att) {
                float a = g_att[t*64 + b];
                hn = a*hn + (1.f - a)*hpr[idx];
                cn = a*cn + (1.f - a)*cold;
            }
            csm[idx] = cn;
            hpr[idx] = hn;
            __stcg(&hout[j*64 + b], hn);
            if (t == len[b] - 1) g_last[b*Hv + j] = hn;
        }
        __syncthreads();   // all stores of this step issued before leader releases

        if (t < Tv - 1) {  // grid barrier (proven R12 form)
            if (tid == 0) {
                __threadfence();
                atomicAdd(&g_bar, 1);
                int tgt = NCTA * (t + 1);
                while (*(volatile int*)&g_bar < tgt) { }
                __threadfence();
            }
            __syncthreads();
        }
    }
}

__global__ void k_logits(const float* __restrict__ Wout, const float* __restrict__ bout,
                         float* __restrict__ out) {
    int wid = (blockIdx.x * blockDim.x + threadIdx.x) >> 5;
    int lane = threadIdx.x & 31;
    if (wid >= Bv*Ov) return;
    int b = wid / Ov, o = wid % Ov;
    float s = 0.f;
    for (int j = lane; j < Hv; j += 32) s += g_last[b*Hv + j] * Wout[(size_t)o*Hv + j];
    #pragma unroll
    for (int off = 16; off; off >>= 1) s += __shfl_xor_sync(0xffffffffu, s, off);
    if (!lane) out[b*Ov + o] = s + bout[o];
}

// ---------------- launch ----------------
extern "C" void kernel_launch(void* const* d_in, const int* in_sizes, int n_in,
                              void* d_out, int out_size) {
    const float* emb  = (const float*)d_in[0];
    const float* Wih  = (const float*)d_in[1];
    const float* bih  = (const float*)d_in[2];
    const float* Whh  = (const float*)d_in[3];
    const float* bhh  = (const float*)d_in[4];
    const float* aW1  = (const float*)d_in[5];
    const float* ab1  = (const float*)d_in[6];
    const float* aW2  = (const float*)d_in[7];
    const float* ab2  = (const float*)d_in[8];
    const float* Wout = (const float*)d_in[9];
    const float* bout = (const float*)d_in[10];
    const int*   x    = (const int*)d_in[11];
    float* out = (float*)d_out;
    (void)in_sizes; (void)n_in; (void)out_size;

    static int smem_set = 0;
    const int PSMEM = (26112 + 64) * 4;
    if (!smem_set) {
        cudaFuncSetAttribute(k_persist, cudaFuncAttributeMaxDynamicSharedMemorySize, PSMEM);
        smem_set = 1;
    }

    k_len<<<1, 64>>>(x);
    k_embed<<<(Tv*Bv*EP + 255)/256, 256>>>(emb, x);
    k_padW<<<(GROWS*EP + 255)/256, 256>>>(Wih);
    k_padA<<<(EP*EP + 255)/256, 256>>>(aW1);
    k_wblk<<<(NCTA*Hv*16 + 255)/256, 256>>>(Whh);

    // one GEMM feeds both iterations (input-side gates are time-invariant across iters)
    dim3 gig(GROWS/64, Tv*Bv/64);
    k_gemm<<<gig, 256>>>(bih, bhh, 0);

    // ---- iteration 0 (persistent) ----
    k_zero<<<(Hv*Bv + 255)/256, 256>>>();
    k_persist<<<NCTA, 128, PSMEM>>>(0);

    // ---- attention (uses g_last from iter 0) ----
    k_part2<<<(Bv*Ev*32 + 255)/256, 256>>>(aW1, ab1);
    dim3 gh1(EP/64, Tv*Bv/64);
    k_gemm<<<gh1, 256>>>((const float*)0, (const float*)0, 1);
    k_att<<<(Tv*Bv*32 + 255)/256, 256>>>(aW2, ab2);

    // ---- iteration 1 (persistent) ----
    k_reinit<<<(Hv*Bv + 255)/256, 256>>>();
    k_persist<<<NCTA, 128, PSMEM>>>(1);

    k_logits<<<(Bv*Ov*32 + 255)/256, 256>>>(Wout, bout, out);
}

// round 16
// speedup vs baseline: 1.4783x; 1.2635x over previous
#include <cuda_runtime.h>
#include <cuda_bf16.h>
#include <math.h>
#include <stdint.h>

#define Bv 64
#define Tv 256
#define Ev 300
#define EP 320          // padded K for the input GEMMs (zeros in pad cols)
#define Hv 512
#define Ov 5
#define PADTOK 1
#define GROWS 2048      // 4*H gate rows
#define NCTA 128        // recurrent CTAs; each owns 4 hidden units = 16 gate rows

// ---------------- scratch (static device allocations; no cudaMalloc) ----------------
__device__ float g_inp [Tv*Bv*EP];                 // [t][b][e], e padded to 320, pad = 0
__device__ float g_Wpad[GROWS*EP];                 // W_ih zero-padded [2048][320]
__device__ float g_Apad[EP*EP];                    // aW1[:,0:300] zero-padded [320][320]
__device__ float g_ig  [Tv*NCTA*16*Bv];            // [t][c][rr][b]  (rr = u*4+q)
__device__ uint4 g_Wfrag[NCTA*32*2*32];            // mma A fragments: [c][kt][term][lane] x uint4
__device__ __nv_bfloat16 g_htA_hi[Bv*Hv];          // h ping, transposed [b][j], bf16 hi
__device__ __nv_bfloat16 g_htA_lo[Bv*Hv];          // residual lo
__device__ __nv_bfloat16 g_htB_hi[Bv*Hv];          // h pong
__device__ __nv_bfloat16 g_htB_lo[Bv*Hv];
__device__ float g_last[Bv*Hv];                    // [b][j] fp32
__device__ float g_att [Tv*Bv];                    // [t][b]
__device__ float g_part2[Bv*Ev];                   // [b][e]
__device__ float g_H1  [Tv*Bv*Ev];                 // [m][e]  tanh(layer1)
__device__ int   g_len [Bv];
__device__ int   g_bar;                            // grid barrier counter

__device__ __forceinline__ float sigf(float x) { return 1.f / (1.f + expf(-x)); }

__device__ __forceinline__ uint32_t smem_u32(const void* p) {
    uint32_t a;
    asm("{ .reg .u64 t; cvta.to.shared.u64 t, %1; cvt.u32.u64 %0, t; }" : "=r"(a) : "l"(p));
    return a;
}

__device__ __forceinline__ uint32_t pkbf(float x, float y) {
    __nv_bfloat162 t;
    t.x = __float2bfloat16(x);
    t.y = __float2bfloat16(y);
    return *(uint32_t*)&t;
}

// mma.sync m16n8k16 row.col bf16 -> f32 accum
__device__ __forceinline__ void mm(float* d, uint4 a, uint32_t b0, uint32_t b1) {
    asm volatile(
        "mma.sync.aligned.m16n8k16.row.col.f32.bf16.bf16.f32 "
        "{%0,%1,%2,%3}, {%4,%5,%6,%7}, {%8,%9}, {%0,%1,%2,%3};"
        : "+f"(d[0]), "+f"(d[1]), "+f"(d[2]), "+f"(d[3])
        : "r"(a.x), "r"(a.y), "r"(a.z), "r"(a.w), "r"(b0), "r"(b1));
}

// ---------------- tiny kernels ----------------
__global__ void k_len(const int* __restrict__ x) {
    int b = threadIdx.x;
    if (b < Bv) {
        int c = 0;
        for (int t = 0; t < Tv; t++) c += (x[b*Tv + t] != PADTOK);
        g_len[b] = c;
    }
}

__global__ void k_embed(const float* __restrict__ emb, const int* __restrict__ x) {
    int idx = blockIdx.x * blockDim.x + threadIdx.x;
    if (idx >= Tv*Bv*EP) return;
    int e = idx % EP;
    int m = idx / EP;
    int b = m % Bv;
    int t = m / Bv;
    float v = 0.f;
    if (e < Ev) {
        int tok = x[b*Tv + t];
        if (tok != PADTOK) v = emb[(size_t)tok*Ev + e];   // padding_idx row -> 0
    }
    g_inp[idx] = v;
}

__global__ void k_padW(const float* __restrict__ W) {   // [2048][300] -> [2048][320]
    int idx = blockIdx.x * blockDim.x + threadIdx.x;
    if (idx >= GROWS*EP) return;
    int k = idx % EP, n = idx / EP;
    g_Wpad[idx] = (k < Ev) ? W[(size_t)n*Ev + k] : 0.f;
}

__global__ void k_padA(const float* __restrict__ aW1) { // [300][812] cols 0:300 -> [320][320]
    int idx = blockIdx.x * blockDim.x + threadIdx.x;
    if (idx >= EP*EP) return;
    int k = idx % EP, n = idx / EP;
    g_Apad[idx] = (n < Ev && k < Ev) ? aW1[(size_t)n*(Ev + Hv) + k] : 0.f;
}

// Build mma A-fragments of W_hh for each CTA: rows rr=0..15 <-> global row (c*4+(rr>>2)) + (rr&3)*512.
// term 0 = bf16(hi), term 1 = bf16(residual). a0:(g,k0..k0+1) a1:(g+8,k0..) a2:(g,k0+8..) a3:(g+8,k0+8..)
__global__ void k_wfrag(const float* __restrict__ Whh) {
    int idx = blockIdx.x * blockDim.x + threadIdx.x;
    if (idx >= NCTA*32*2*32) return;
    int lane = idx & 31, term = (idx >> 5) & 1, kt = (idx >> 6) & 31, c = idx >> 11;
    int g4 = lane >> 2, q4 = lane & 3;
    int k0 = kt*16 + q4*2;
    uint32_t regs[4];
    #pragma unroll
    for (int rs = 0; rs < 4; rs++) {
        int r  = g4 + ((rs & 1) ? 8 : 0);
        int kk = k0 + ((rs >> 1) ? 8 : 0);
        int rg = (c*4 + (r >> 2)) + (r & 3)*Hv;
        float2 wv = *(const float2*)&Whh[(size_t)rg*Hv + kk];
        float xx = wv.x, yy = wv.y;
        if (term) {
            xx = xx - __bfloat162float(__float2bfloat16(xx));
            yy = yy - __bfloat162float(__float2bfloat16(yy));
        }
        regs[rs] = pkbf(xx, yy);
    }
    g_Wfrag[idx] = make_uint4(regs[0], regs[1], regs[2], regs[3]);
}

__global__ void k_zero() {
    int i = blockIdx.x * blockDim.x + threadIdx.x;
    if (i == 0) g_bar = 0;
    if (i < Bv*Hv) {
        g_htA_hi[i] = __float2bfloat16(0.f);
        g_htA_lo[i] = __float2bfloat16(0.f);
    }
}

__global__ void k_reinit() {   // h <- last (hi/lo bf16) for iteration 1
    int i = blockIdx.x * blockDim.x + threadIdx.x;
    if (i == 0) g_bar = 0;
    if (i < Bv*Hv) {
        float v = g_last[i];
        __nv_bfloat16 hi = __float2bfloat16(v);
        g_htA_hi[i] = hi;
        g_htA_lo[i] = __float2bfloat16(v - __bfloat162float(hi));
    }
}

// ---------------- time-parallel GEMM (proven R15): C[m][n] = sum_k g_inp[m][k] * Bm[n][k] ---------
__global__ void k_gemm(const float* __restrict__ bias1, const float* __restrict__ bias2,
                       int mode) {
    __shared__ float As[2][32][68];
    __shared__ float Bs[2][32][68];
    const float* __restrict__ Bm = (mode == 0) ? g_Wpad : g_Apad;  // device-side symbol
    int tid = threadIdx.x;
    int m0 = blockIdx.y * 64, n0 = blockIdx.x * 64;
    int lr = tid >> 2;
    int lk = (tid & 3) * 8;
    int tx = tid & 15, ty = tid >> 4;
    float acc[4][4] = {};

    const float* Ap = g_inp + (size_t)(m0 + lr)*EP + lk;
    const float* Bp = Bm    + (size_t)(n0 + lr)*EP + lk;

    float4 a0 = *(const float4*)(Ap);
    float4 a1 = *(const float4*)(Ap + 4);
    float4 b0 = *(const float4*)(Bp);
    float4 b1 = *(const float4*)(Bp + 4);

    #pragma unroll 1
    for (int t = 0; t < EP/32; t++) {
        int buf = t & 1;
        As[buf][lk+0][lr] = a0.x; As[buf][lk+1][lr] = a0.y;
        As[buf][lk+2][lr] = a0.z; As[buf][lk+3][lr] = a0.w;
        As[buf][lk+4][lr] = a1.x; As[buf][lk+5][lr] = a1.y;
        As[buf][lk+6][lr] = a1.z; As[buf][lk+7][lr] = a1.w;
        Bs[buf][lk+0][lr] = b0.x; Bs[buf][lk+1][lr] = b0.y;
        Bs[buf][lk+2][lr] = b0.z; Bs[buf][lk+3][lr] = b0.w;
        Bs[buf][lk+4][lr] = b1.x; Bs[buf][lk+5][lr] = b1.y;
        Bs[buf][lk+6][lr] = b1.z; Bs[buf][lk+7][lr] = b1.w;
        __syncthreads();
        if (t + 1 < EP/32) {
            int kb = (t + 1) * 32;
            a0 = *(const float4*)(Ap + kb);
            a1 = *(const float4*)(Ap + kb + 4);
            b0 = *(const float4*)(Bp + kb);
            b1 = *(const float4*)(Bp + kb + 4);
        }
        #pragma unroll
        for (int kk = 0; kk < 32; kk++) {
            float4 a = *(const float4*)&As[buf][kk][ty*4];
            float4 bb = *(const float4*)&Bs[buf][kk][tx*4];
            acc[0][0] += a.x*bb.x; acc[0][1] += a.x*bb.y; acc[0][2] += a.x*bb.z; acc[0][3] += a.x*bb.w;
            acc[1][0] += a.y*bb.x; acc[1][1] += a.y*bb.y; acc[1][2] += a.y*bb.z; acc[1][3] += a.y*bb.w;
            acc[2][0] += a.z*bb.x; acc[2][1] += a.z*bb.y; acc[2][2] += a.z*bb.z; acc[2][3] += a.z*bb.w;
            acc[3][0] += a.w*bb.x; acc[3][1] += a.w*bb.y; acc[3][2] += a.w*bb.z; acc[3][3] += a.w*bb.w;
        }
        __syncthreads();
    }

    #pragma unroll
    for (int i = 0; i < 4; i++) {
        int m = m0 + ty*4 + i;
        int t = m >> 6, b = m & 63;
        #pragma unroll
        for (int j = 0; j < 4; j++) {
            int n = n0 + tx*4 + j;
            if (mode == 0) {
                float v = acc[i][j] + bias1[n] + bias2[n];
                int q = n >> 9, jj = n & (Hv - 1);
                int cc = jj >> 2, u = jj & 3, rr = u*4 + q;
                g_ig[(((size_t)t*NCTA + cc)*16 + rr)*64 + b] = v;
            } else if (n < Ev) {
                g_H1[(size_t)m*Ev + n] = tanhf(acc[i][j] + g_part2[b*Ev + n]);
            }
        }
    }
}

// part2[b][e] = ab1[e] + sum_k last[b][k] * aW1[e][300+k]
__global__ void k_part2(const float* __restrict__ aW1, const float* __restrict__ ab1) {
    int wid = (blockIdx.x * blockDim.x + threadIdx.x) >> 5;
    int lane = threadIdx.x & 31;
    if (wid >= Bv*Ev) return;
    int b = wid / Ev, e = wid % Ev;
    const float* lp = g_last + b*Hv;
    const float* wp = aW1 + (size_t)e*(Ev + Hv) + Ev;
    float s = 0.f;
    for (int k = lane; k < Hv; k += 32) s += lp[k] * wp[k];
    #pragma unroll
    for (int o = 16; o; o >>= 1) s += __shfl_xor_sync(0xffffffffu, s, o);
    if (!lane) g_part2[b*Ev + e] = s + ab1[e];
}

// att[m] = sigmoid(ab2 + sum_e H1[m][e]*aW2[e])
__global__ void k_att(const float* __restrict__ aW2, const float* __restrict__ ab2) {
    int wid = (blockIdx.x * blockDim.x + threadIdx.x) >> 5;
    int lane = threadIdx.x & 31;
    if (wid >= Tv*Bv) return;
    const float* hp = g_H1 + (size_t)wid*Ev;
    float s = 0.f;
    for (int e = lane; e < Ev; e += 32) s += hp[e] * aW2[e];
    #pragma unroll
    for (int o = 16; o; o >>= 1) s += __shfl_xor_sync(0xffffffffu, s, o);
    if (!lane) g_att[wid] = sigf(s + ab2[0]);
}

// ---------------- persistent recurrent kernel (tensor-core bf16x3) ----------------
// 128 CTAs x 128 threads. CTA c owns gate rows rr=0..15 (hidden units 4c..4c+3).
// Per step: gates[16x64] = W[16x512] @ h[512x64] via mma.sync m16n8k16 bf16 Markidis-3.
// h exchanged as transposed bf16 hi/lo [b][j] global ping-pong, cp.async by K-slices.
#define CP_WAIT(N) asm volatile("cp.async.wait_group " #N ";\n" ::: "memory")
#define HSTR 260   // u32 stride of one b-row in SMEM h buffers (256 data + 4 pad)

__global__ void __launch_bounds__(128, 1) k_persist(int use_att) {
    extern __shared__ char smraw[];
    uint4*    WsmU4 = (uint4*)smraw;                        // 32768 B : A fragments
    uint32_t* Hhi   = (uint32_t*)(smraw + 32768);           // 66560 B : h hi [b][k] bf16x2
    uint32_t* Hlo   = (uint32_t*)(smraw + 99328);           // 66560 B
    float*    Gs    = (float*)(smraw + 165888);             // 16 x 68 floats
    int*      len   = (int*)(smraw + 170240);               // 64 ints

    int tid = threadIdx.x, w = tid >> 5, lane = tid & 31;
    int c = blockIdx.x;
    uint32_t hhi_b = smem_u32(Hhi), hlo_b = smem_u32(Hlo);

    { // resident W fragments (loaded once, reused 256 steps)
        const uint4* wf = g_Wfrag + (size_t)c*2048;
        for (int i = tid; i < 2048; i += 128) WsmU4[i] = wf[i];
    }
    if (tid < 64) len[tid] = g_len[tid];
    __syncthreads();

    // epilogue ownership: thread -> (unit ue, batch be) and (ue+2, be)
    int ue = tid >> 6, be = tid & 63;
    int j0 = c*4 + ue, j1 = c*4 + ue + 2;
    float cst0 = 0.f, cst1 = 0.f;
    float hp0 = use_att ? g_last[be*Hv + j0] : 0.f;
    float hp1 = use_att ? g_last[be*Hv + j1] : 0.f;
    int lim = len[be] - 1;

    int g4 = lane >> 2, q4 = lane & 3;
    int w16 = w * 16;

    for (int t = 0; t < Tv; t++) {
        const __nv_bfloat16* ghi = (t & 1) ? g_htB_hi : g_htA_hi;
        const __nv_bfloat16* glo = (t & 1) ? g_htB_lo : g_htA_lo;
        __nv_bfloat16* ohi = (t & 1) ? g_htA_hi : g_htB_hi;
        __nv_bfloat16* olo = (t & 1) ? g_htA_lo : g_htB_lo;

        // issue all 4 k-slice groups (hi+lo) up front
        #pragma unroll
        for (int g = 0; g < 4; g++) {
            #pragma unroll
            for (int i = 0; i < 8; i++) {
                int ch = tid + i*128;                 // 0..1023
                int b = ch >> 4, off = (ch & 15) * 16;
                uint32_t dst = (uint32_t)(b*1040 + g*256 + off);
                const char* src = (const char*)ghi + b*1024 + g*256 + off;
                asm volatile("cp.async.cg.shared.global [%0], [%1], 16;\n"
                             :: "r"(hhi_b + dst), "l"(src));
            }
            #pragma unroll
            for (int i = 0; i < 8; i++) {
                int ch = tid + i*128;
                int b = ch >> 4, off = (ch & 15) * 16;
                uint32_t dst = (uint32_t)(b*1040 + g*256 + off);
                const char* src = (const char*)glo + b*1024 + g*256 + off;
                asm volatile("cp.async.cg.shared.global [%0], [%1], 16;\n"
                             :: "r"(hlo_b + dst), "l"(src));
            }
            asm volatile("cp.async.commit_group;\n" ::: "memory");
        }

        // input-side gate prefetch (consumed in epilogue)
        const float* igc = g_ig + ((size_t)t*NCTA + c)*1024;
        float igv[8];
        #pragma unroll
        for (int q = 0; q < 4; q++) {
            igv[q]     = igc[(ue*4 + q)*64 + be];
            igv[4 + q] = igc[((ue + 2)*4 + q)*64 + be];
        }

        float dA0[4] = {}, dB0[4] = {}, dC0[4] = {};
        float dA1[4] = {}, dB1[4] = {}, dC1[4] = {};

        #pragma unroll
        for (int g = 0; g < 4; g++) {
            if (g == 0) { CP_WAIT(3); } else if (g == 1) { CP_WAIT(2); }
            else if (g == 2) { CP_WAIT(1); } else { CP_WAIT(0); }
            __syncthreads();
            #pragma unroll
            for (int kti = 0; kti < 8; kti++) {
                int kt = g*8 + kti;
                uint4 A1 = WsmU4[(kt*2 + 0)*32 + lane];
                uint4 A2 = WsmU4[(kt*2 + 1)*32 + lane];
                int bi0 = (w16 + g4)*HSTR + kt*8 + q4;       // ntile 0
                uint32_t b0h = Hhi[bi0],            b1h = Hhi[bi0 + 4];
                uint32_t b0l = Hlo[bi0],            b1l = Hlo[bi0 + 4];
                mm(dA0, A1, b0h, b1h);
                mm(dB0, A1, b0l, b1l);
                mm(dC0, A2, b0h, b1h);
                int bi1 = bi0 + 8*HSTR;                      // ntile 1 (+8 batch cols)
                uint32_t c0h = Hhi[bi1],            c1h = Hhi[bi1 + 4];
                uint32_t c0l = Hlo[bi1],            c1l = Hlo[bi1 + 4];
                mm(dA1, A1, c0h, c1h);
                mm(dB1, A1, c0l, c1l);
                mm(dC1, A2, c0h, c1h);
            }
        }

        // stage gates: D(row,col) -> Gs[row][col], rows=rr, cols=b
        {
            float* p = &Gs[g4*68 + w16 + q4*2];
            *(float2*)p            = make_float2(dA0[0]+dB0[0]+dC0[0], dA0[1]+dB0[1]+dC0[1]);
            *(float2*)(p + 8*68)   = make_float2(dA0[2]+dB0[2]+dC0[2], dA0[3]+dB0[3]+dC0[3]);
            *(float2*)(p + 8)      = make_float2(dA1[0]+dB1[0]+dC1[0], dA1[1]+dB1[1]+dC1[1]);
            *(float2*)(p + 8*68+8) = make_float2(dA1[2]+dB1[2]+dC1[2], dA1[3]+dB1[3]+dC1[3]);
        }
        __syncthreads();

        // LSTM cell (+ optional attention gate); state in registers
        float a = 1.f, am = 0.f;
        if (use_att) { a = g_att[t*64 + be]; am = 1.f - a; }
        {
            float gi = Gs[(ue*4 + 0)*68 + be] + igv[0];
            float gf = Gs[(ue*4 + 1)*68 + be] + igv[1];
            float gg = Gs[(ue*4 + 2)*68 + be] + igv[2];
            float go = Gs[(ue*4 + 3)*68 + be] + igv[3];
            float cn = sigf(gf)*cst0 + sigf(gi)*tanhf(gg);
            float hn = sigf(go)*tanhf(cn);
            if (use_att) { hn = a*hn + am*hp0; cn = a*cn + am*cst0; }
            cst0 = cn; hp0 = hn;
            __nv_bfloat16 bh = __float2bfloat16(hn);
            ohi[be*Hv + j0] = bh;
            olo[be*Hv + j0] = __float2bfloat16(hn - __bfloat162float(bh));
            if (t == lim) g_last[be*Hv + j0] = hn;
        }
        {
            float gi = Gs[((ue+2)*4 + 0)*68 + be] + igv[4];
            float gf = Gs[((ue+2)*4 + 1)*68 + be] + igv[5];
            float gg = Gs[((ue+2)*4 + 2)*68 + be] + igv[6];
            float go = Gs[((ue+2)*4 + 3)*68 + be] + igv[7];
            float cn = sigf(gf)*cst1 + sigf(gi)*tanhf(gg);
            float hn = sigf(go)*tanhf(cn);
            if (use_att) { hn = a*hn + am*hp1; cn = a*cn + am*cst1; }
            cst1 = cn; hp1 = hn;
            __nv_bfloat16 bh = __float2bfloat16(hn);
            ohi[be*Hv + j1] = bh;
            olo[be*Hv + j1] = __float2bfloat16(hn - __bfloat162float(bh));
            if (t == lim) g_last[be*Hv + j1] = hn;
        }
        __syncthreads();   // all stores of this step issued before leader releases

        if (t < Tv - 1) {  // grid barrier (proven R12 form)
            if (tid == 0) {
                __threadfence();
                atomicAdd(&g_bar, 1);
                int tgt = NCTA * (t + 1);
                while (*(volatile int*)&g_bar < tgt) { }
                __threadfence();
            }
            __syncthreads();
        }
    }
}

__global__ void k_logits(const float* __restrict__ Wout, const float* __restrict__ bout,
                         float* __restrict__ out) {
    int wid = (blockIdx.x * blockDim.x + threadIdx.x) >> 5;
    int lane = threadIdx.x & 31;
    if (wid >= Bv*Ov) return;
    int b = wid / Ov, o = wid % Ov;
    float s = 0.f;
    for (int j = lane; j < Hv; j += 32) s += g_last[b*Hv + j] * Wout[(size_t)o*Hv + j];
    #pragma unroll
    for (int off = 16; off; off >>= 1) s += __shfl_xor_sync(0xffffffffu, s, off);
    if (!lane) out[b*Ov + o] = s + bout[o];
}

// ---------------- launch ----------------
extern "C" void kernel_launch(void* const* d_in, const int* in_sizes, int n_in,
                              void* d_out, int out_size) {
    const float* emb  = (const float*)d_in[0];
    const float* Wih  = (const float*)d_in[1];
    const float* bih  = (const float*)d_in[2];
    const float* Whh  = (const float*)d_in[3];
    const float* bhh  = (const float*)d_in[4];
    const float* aW1  = (const float*)d_in[5];
    const float* ab1  = (const float*)d_in[6];
    const float* aW2  = (const float*)d_in[7];
    const float* ab2  = (const float*)d_in[8];
    const float* Wout = (const float*)d_in[9];
    const float* bout = (const float*)d_in[10];
    const int*   x    = (const int*)d_in[11];
    float* out = (float*)d_out;
    (void)in_sizes; (void)n_in; (void)out_size;

    static int smem_set = 0;
    const int PSMEM = 170496;   // Wfrag 32K + h hi/lo 2x65K + Gs + len
    if (!smem_set) {
        cudaFuncSetAttribute(k_persist, cudaFuncAttributeMaxDynamicSharedMemorySize, PSMEM);
        smem_set = 1;
    }

    k_len<<<1, 64>>>(x);
    k_embed<<<(Tv*Bv*EP + 255)/256, 256>>>(emb, x);
    k_padW<<<(GROWS*EP + 255)/256, 256>>>(Wih);
    k_padA<<<(EP*EP + 255)/256, 256>>>(aW1);
    k_wfrag<<<(NCTA*32*2*32 + 255)/256, 256>>>(Whh);

    // one GEMM feeds both iterations (input-side gates are time-invariant across iters)
    dim3 gig(GROWS/64, Tv*Bv/64);
    k_gemm<<<gig, 256>>>(bih, bhh, 0);

    // ---- iteration 0 (persistent, tensor-core) ----
    k_zero<<<(Bv*Hv + 255)/256, 256>>>();
    k_persist<<<NCTA, 128, PSMEM>>>(0);

    // ---- attention (uses g_last from iter 0) ----
    k_part2<<<(Bv*Ev*32 + 255)/256, 256>>>(aW1, ab1);
    dim3 gh1(EP/64, Tv*Bv/64);
    k_gemm<<<gh1, 256>>>((const float*)0, (const float*)0, 1);
    k_att<<<(Tv*Bv*32 + 255)/256, 256>>>(aW2, ab2);

    // ---- iteration 1 (persistent, tensor-core) ----
    k_reinit<<<(Bv*Hv + 255)/256, 256>>>();
    k_persist<<<NCTA, 128, PSMEM>>>(1);

    k_logits<<<(Bv*Ov*32 + 255)/256, 256>>>(Wout, bout, out);
}